// round 8
// baseline (speedup 1.0000x reference)
#include <cuda_runtime.h>
#include <cuda_fp16.h>
#include <math.h>
#include <stdint.h>

// ============================================================================
// Problem dims
// ============================================================================
#define B_ 64
#define T_ 128
#define S_ 1024
#define I_ 1024
#define O_ 1024
#define M_ (B_*T_)   // 8192
#define C_ (I_+O_)   // 2048

// ============================================================================
// Scratch (__device__ globals; allocation-free rule). fp16 2-way splits (h|l).
// ============================================================================
__device__ __half g_wa2[I_ * 2 * O_];                    // [1024, 2048]
__device__ __half g_qp2[M_ * 2 * I_];                    // [8192, 2048]
__device__ __half g_enc2[(size_t)B_ * S_ * 2 * I_];      // [64][1024, 2048]
__device__ __half g_encT2[(size_t)B_ * I_ * 2 * S_];     // [64][1024, 2048] transposed
__device__ __half g_w2[M_ * 2 * S_];                     // [8192, 2048]
__device__ __half g_cat2[(size_t)M_ * 2 * C_];           // [8192, 4096] row=[ctx_h|dec_h|ctx_l|dec_l]
__device__ __half g_wo2[O_ * 2 * C_];                    // [1024, 4096]

// ============================================================================
// Helpers
// ============================================================================
__device__ __forceinline__ uint32_t smem_u32(const void* p) {
    uint32_t a;
    asm("{ .reg .u64 t; cvta.to.shared.u64 t, %1; cvt.u32.u64 %0, t; }" : "=r"(a) : "l"(p));
    return a;
}

__device__ __forceinline__ void ldsm4(uint32_t r[4], uint32_t addr) {
    asm volatile("ldmatrix.sync.aligned.m8n8.x4.shared.b16 {%0,%1,%2,%3}, [%4];"
        : "=r"(r[0]), "=r"(r[1]), "=r"(r[2]), "=r"(r[3]) : "r"(addr));
}

__device__ __forceinline__ void mma_fp16(float d[4], const uint32_t a[4], const uint32_t b[2]) {
    asm volatile(
        "mma.sync.aligned.m16n8k16.row.col.f32.f16.f16.f32 "
        "{%0,%1,%2,%3}, {%4,%5,%6,%7}, {%8,%9}, {%0,%1,%2,%3};"
        : "+f"(d[0]), "+f"(d[1]), "+f"(d[2]), "+f"(d[3])
        : "r"(a[0]), "r"(a[1]), "r"(a[2]), "r"(a[3]), "r"(b[0]), "r"(b[1]));
}

__device__ __forceinline__ void split2h(float x, __half& h, __half& l) {
    h = __float2half_rn(x);
    l = __float2half_rn(x - __half2float(h));
}

#define CP_ASYNC16(dst, src) \
    asm volatile("cp.async.cg.shared.global [%0], [%1], 16;" :: "r"(dst), "l"(src))
#define CP_COMMIT() asm volatile("cp.async.commit_group;" ::: "memory")
#define CP_WAIT1()  asm volatile("cp.async.wait_group 1;" ::: "memory")
#define CP_WAIT0()  asm volatile("cp.async.wait_group 0;" ::: "memory")

// ============================================================================
// HMMA GEMM, fp16 2-way split (3 passes: hh, hl, lh), NT, K-major.
// Operands: A[rows, pitchA] slabs at sA*slabA; B[rows, pitchB] slabs at s*slabB.
// CTA tile 128(M) x 256(N), BK=64, 2-stage cp.async, 512 threads (16 warps 2x8),
// warp tile 64x32.
// EPI: 0 = fp32 store, 1 = tanh(acc+bias) fp32, 2 = split2h half store
// ============================================================================
#define TB_A 16384                       // 128x64 half tile bytes
#define TB_B 32768                       // 256x64 half tile bytes
#define STAGEB (2*TB_A + 2*TB_B)         // 98304
#define OFF_B (2*TB_A)

template<int EPI>
__global__ void __launch_bounds__(512, 1) tgemm(
    const __half* __restrict__ A, const __half* __restrict__ B,
    float* __restrict__ Cf, __half* __restrict__ Cs,
    const float* __restrict__ bias,
    int K, int pitchA, int pitchB, int slabA, int slabB,
    long long sA, long long sB, long long sC,
    int ldc, int splitOff)
{
    extern __shared__ char smem[];
    const uint32_t sb = smem_u32(smem);
    const int tid = threadIdx.x;
    const int lane = tid & 31, wid = tid >> 5;
    const int wm = wid & 1, wn = wid >> 1;        // warp tile (wm*64, wn*32), wn 0..7
    const int n0 = blockIdx.x * 256, m0 = blockIdx.y * 128;
    const long long z = blockIdx.z;

    const __half* Ab = A + z * sA;
    const __half* Bb = B + z * sB;

    const int PA[3] = {0, 0, 1};
    const int PB[3] = {0, 1, 0};

    const int nchunk = K >> 6;

    float acc[4][4][4];
    #pragma unroll
    for (int i = 0; i < 4; i++)
        #pragma unroll
        for (int j = 0; j < 4; j++)
            #pragma unroll
            for (int q = 0; q < 4; q++) acc[i][j][q] = 0.f;

    // ldmatrix lane-address components
    const int g = lane >> 3, lr = lane & 7;
    const int a_r  = lr + (g & 1) * 8;
    const int a_kb = (g >> 1) * 16;
    const int b_r  = lr + (g >> 1) * 8;
    const int b_kb = (g & 1) * 16;

    auto prefetch = [&](int c, int stage) {
        const int k0 = c << 6;
        const uint32_t sbase = sb + stage * STAGEB;
        #pragma unroll
        for (int s = 0; s < 2; s++) {
            #pragma unroll
            for (int j = 0; j < 2; j++) {        // A: 128 rows x 64 cols
                int v = tid + 512 * j;
                int r = v >> 3, cc = (v & 7) << 3;
                uint32_t off = (uint32_t)(r * 128 + cc * 2);
                off ^= (off >> 3) & 0x70u;
                CP_ASYNC16(sbase + s * TB_A + off,
                           Ab + (long long)(m0 + r) * pitchA + s * slabA + k0 + cc);
            }
            #pragma unroll
            for (int j = 0; j < 4; j++) {        // B: 256 rows x 64 cols
                int v = tid + 512 * j;
                int r = v >> 3, cc = (v & 7) << 3;
                uint32_t off = (uint32_t)(r * 128 + cc * 2);
                off ^= (off >> 3) & 0x70u;
                CP_ASYNC16(sbase + OFF_B + s * TB_B + off,
                           Bb + (long long)(n0 + r) * pitchB + s * slabB + k0 + cc);
            }
        }
    };

    prefetch(0, 0);
    CP_COMMIT();

    for (int c = 0; c < nchunk; c++) {
        const int stage = c & 1;
        if (c + 1 < nchunk) {
            prefetch(c + 1, stage ^ 1);
            CP_COMMIT();
            CP_WAIT1();
        } else {
            CP_WAIT0();
        }
        __syncthreads();

        const uint32_t sbase = sb + stage * STAGEB;
        #pragma unroll
        for (int p = 0; p < 3; p++) {
            const uint32_t aBase = sbase + PA[p] * TB_A;
            const uint32_t bBase = sbase + OFF_B + PB[p] * TB_B;
            #pragma unroll
            for (int kt = 0; kt < 4; kt++) {
                uint32_t afr[4][4], bfr[2][4];
                #pragma unroll
                for (int mt = 0; mt < 4; mt++) {
                    uint32_t off = (uint32_t)((wm * 64 + mt * 16 + a_r) * 128 + kt * 32 + a_kb);
                    off ^= (off >> 3) & 0x70u;
                    ldsm4(afr[mt], aBase + off);
                }
                #pragma unroll
                for (int ntp = 0; ntp < 2; ntp++) {
                    uint32_t off = (uint32_t)((wn * 32 + ntp * 16 + b_r) * 128 + kt * 32 + b_kb);
                    off ^= (off >> 3) & 0x70u;
                    ldsm4(bfr[ntp], bBase + off);
                }
                #pragma unroll
                for (int mt = 0; mt < 4; mt++)
                    #pragma unroll
                    for (int nt = 0; nt < 4; nt++)
                        mma_fp16(acc[mt][nt], afr[mt], &bfr[nt >> 1][(nt & 1) * 2]);
            }
        }
        __syncthreads();
    }

    // ---- epilogue ----
    const int qr = lane >> 2;
    const int qc = (lane & 3) * 2;
    #pragma unroll
    for (int mt = 0; mt < 4; mt++) {
        #pragma unroll
        for (int nt = 0; nt < 4; nt++) {
            const long long row0 = m0 + wm * 64 + mt * 16 + qr;
            const long long row1 = row0 + 8;
            const int col = n0 + wn * 32 + nt * 8 + qc;
            float v00 = acc[mt][nt][0], v01 = acc[mt][nt][1];
            float v10 = acc[mt][nt][2], v11 = acc[mt][nt][3];
            if (EPI == 0) {
                *reinterpret_cast<float2*>(Cf + z * sC + row0 * ldc + col) = make_float2(v00, v01);
                *reinterpret_cast<float2*>(Cf + z * sC + row1 * ldc + col) = make_float2(v10, v11);
            } else if (EPI == 1) {
                float b0 = bias[col], b1 = bias[col + 1];
                *reinterpret_cast<float2*>(Cf + z * sC + row0 * ldc + col) =
                    make_float2(tanhf(v00 + b0), tanhf(v01 + b1));
                *reinterpret_cast<float2*>(Cf + z * sC + row1 * ldc + col) =
                    make_float2(tanhf(v10 + b0), tanhf(v11 + b1));
            } else {
                __half h0, l0, h1, l1;
                split2h(v00, h0, l0); split2h(v01, h1, l1);
                *reinterpret_cast<__half2*>(Cs + z * sC + row0 * ldc + col) = __halves2half2(h0, h1);
                *reinterpret_cast<__half2*>(Cs + z * sC + row0 * ldc + splitOff + col) = __halves2half2(l0, l1);
                split2h(v10, h0, l0); split2h(v11, h1, l1);
                *reinterpret_cast<__half2*>(Cs + z * sC + row1 * ldc + col) = __halves2half2(h0, h1);
                *reinterpret_cast<__half2*>(Cs + z * sC + row1 * ldc + splitOff + col) = __halves2half2(l0, l1);
            }
        }
    }
}

// ============================================================================
// Conversion kernels (fp16 2-way)
// ============================================================================
__global__ void __launch_bounds__(256) split2_kernel(
    const float* __restrict__ src, __half* __restrict__ dst, int K)
{
    long long i = (long long)blockIdx.x * blockDim.x + threadIdx.x;
    long long rr = i / K;
    int k = (int)(i - rr * K);
    __half h, l;
    split2h(src[i], h, l);
    __half* row = dst + rr * (2LL * K);
    row[k] = h; row[K + k] = l;
}

// dec -> cat2 [8192,4096]: row = [ctx_h(0:1024)|dec_h(1024:2048)|ctx_l(2048:3072)|dec_l(3072:4096)]
__global__ void __launch_bounds__(256) dec_to_cat_kernel(
    const float* __restrict__ dec, __half* __restrict__ cat)
{
    long long i = (long long)blockIdx.x * blockDim.x + threadIdx.x;  // 8192*1024
    long long m = i >> 10;
    int o = (int)(i & 1023);
    __half h, l;
    split2h(dec[i], h, l);
    cat[m * 4096 + 1024 + o] = h;
    cat[m * 4096 + 3072 + o] = l;
}

// enc -> enc2 [b][s, 2048] and encT2 [b][i, 2048] (transposed), h|l
__global__ void __launch_bounds__(1024) enc_split_kernel(
    const float* __restrict__ enc, __half* __restrict__ e2, __half* __restrict__ eT2)
{
    __shared__ __half sh[32][33], sl[32][33];
    int b = blockIdx.z;
    int i0 = blockIdx.x * 32, s0 = blockIdx.y * 32;
    int tx = threadIdx.x, ty = threadIdx.y;
    const float* eb = enc + (size_t)b * S_ * I_;
    float x = eb[(size_t)(s0 + ty) * I_ + i0 + tx];
    __half h, l;
    split2h(x, h, l);
    __half* e2b = e2 + (size_t)b * S_ * 2 * I_;
    e2b[(size_t)(s0 + ty) * 2048 + i0 + tx] = h;
    e2b[(size_t)(s0 + ty) * 2048 + 1024 + i0 + tx] = l;
    sh[ty][tx] = h; sl[ty][tx] = l;
    __syncthreads();
    __half* eTb = eT2 + (size_t)b * I_ * 2 * S_;
    eTb[(size_t)(i0 + ty) * 2048 + s0 + tx] = sh[tx][ty];
    eTb[(size_t)(i0 + ty) * 2048 + 1024 + s0 + tx] = sl[tx][ty];
}

// ============================================================================
// Masked softmax over rows of [B*T, S=1024], in place (fp32), fused fp16 split.
// ============================================================================
__device__ __forceinline__ float warpMax(float v) {
    #pragma unroll
    for (int o = 16; o; o >>= 1) v = fmaxf(v, __shfl_xor_sync(0xffffffffu, v, o));
    return v;
}
__device__ __forceinline__ float warpSum(float v) {
    #pragma unroll
    for (int o = 16; o; o >>= 1) v += __shfl_xor_sync(0xffffffffu, v, o);
    return v;
}

__global__ void __launch_bounds__(256) softmax_mask(
    float* __restrict__ w, const int* __restrict__ mask, __half* __restrict__ wsplit)
{
    const int S = 1024;
    long long row = blockIdx.x;
    int b = (int)(row >> 7);
    float* sr = w + row * S;
    const int* mr = mask + (long long)b * S;
    int tid = threadIdx.x;

    float4 v = *reinterpret_cast<const float4*>(sr + tid * 4);
    int4 m = *reinterpret_cast<const int4*>(mr + tid * 4);

    bool msk[4] = {m.x != 0, m.y != 0, m.z != 0, m.w != 0};
    float x[4];
    x[0] = msk[0] ? -INFINITY : v.x;
    x[1] = msk[1] ? -INFINITY : v.y;
    x[2] = msk[2] ? -INFINITY : v.z;
    x[3] = msk[3] ? -INFINITY : v.w;

    float mx = fmaxf(fmaxf(x[0], x[1]), fmaxf(x[2], x[3]));

    __shared__ float sh[8];
    float wm = warpMax(mx);
    if ((tid & 31) == 0) sh[tid >> 5] = wm;
    __syncthreads();
    if (tid < 32) {
        float t = (tid < 8) ? sh[tid] : -INFINITY;
        t = warpMax(t);
        if (tid == 0) sh[0] = t;
    }
    __syncthreads();
    mx = sh[0];

    float e[4], s = 0.f;
    #pragma unroll
    for (int j = 0; j < 4; j++) {
        e[j] = msk[j] ? 0.f : __expf(x[j] - mx);
        s += e[j];
    }
    __syncthreads();
    float ws = warpSum(s);
    if ((tid & 31) == 0) sh[tid >> 5] = ws;
    __syncthreads();
    if (tid < 32) {
        float t = (tid < 8) ? sh[tid] : 0.f;
        t = warpSum(t);
        if (tid == 0) sh[0] = t;
    }
    __syncthreads();
    float inv = 1.0f / sh[0];

    float o[4] = {e[0] * inv, e[1] * inv, e[2] * inv, e[3] * inv};
    float4 of = {o[0], o[1], o[2], o[3]};
    *reinterpret_cast<float4*>(sr + tid * 4) = of;

    __half* wrow = wsplit + row * 2048;
    #pragma unroll
    for (int j = 0; j < 4; j++) {
        __half h, l;
        split2h(o[j], h, l);
        wrow[tid * 4 + j] = h;
        wrow[1024 + tid * 4 + j] = l;
    }
}

// ============================================================================
extern "C" void kernel_launch(void* const* d_in, const int* in_sizes, int n_in,
                              void* d_out, int out_size)
{
    const float* dec    = (const float*)d_in[0];   // [64,128,1024]
    const float* enc    = (const float*)d_in[1];   // [64,1024,1024]
    const int*   mask   = (const int*)d_in[2];     // [64,1024] bool->int32
    const float* W_attn = (const float*)d_in[3];   // [1024,1024]
    const float* W_out  = (const float*)d_in[4];   // [1024,2048]
    const float* b_out  = (const float*)d_in[5];   // [1024]

    float* out     = (float*)d_out;                 // attn_outputs [64,128,1024]
    float* weights = out + (long long)M_ * O_;      // attn_weights [64,128,1024]

    __half *wa2, *qp2, *enc2, *encT2, *w2, *cat2, *wo2;
    cudaGetSymbolAddress((void**)&wa2,   g_wa2);
    cudaGetSymbolAddress((void**)&qp2,   g_qp2);
    cudaGetSymbolAddress((void**)&enc2,  g_enc2);
    cudaGetSymbolAddress((void**)&encT2, g_encT2);
    cudaGetSymbolAddress((void**)&w2,    g_w2);
    cudaGetSymbolAddress((void**)&cat2,  g_cat2);
    cudaGetSymbolAddress((void**)&wo2,   g_wo2);

    const int SMB = 2 * STAGEB;  // 196608
    cudaFuncSetAttribute((const void*)tgemm<0>, cudaFuncAttributeMaxDynamicSharedMemorySize, SMB);
    cudaFuncSetAttribute((const void*)tgemm<1>, cudaFuncAttributeMaxDynamicSharedMemorySize, SMB);
    cudaFuncSetAttribute((const void*)tgemm<2>, cudaFuncAttributeMaxDynamicSharedMemorySize, SMB);

    // --- Conversions ---
    split2_kernel<<<(I_ * (long long)O_) / 256, 256>>>(W_attn, wa2, O_);
    split2_kernel<<<(O_ * (long long)C_) / 256, 256>>>(W_out, wo2, C_);
    enc_split_kernel<<<dim3(I_ / 32, S_ / 32, B_), dim3(32, 32)>>>(enc, enc2, encT2);
    dec_to_cat_kernel<<<(M_ * (long long)O_) / 256, 256>>>(dec, cat2);

    // --- GEMM1: q_proj = dec . W_attn^T  (A = dec slabs inside cat2) -> qp2 ---
    tgemm<2><<<dim3(I_ / 256, M_ / 128, 1), 512, SMB>>>(
        cat2 + 1024, wa2, nullptr, qp2, nullptr,
        O_, /*pitchA*/4096, /*pitchB*/2048, /*slabA*/2048, /*slabB*/1024,
        0, 0, 0, 2 * I_, I_);

    // --- GEMM2: scores[b] = q[b] . enc[b]^T -> weights fp32 ---
    tgemm<0><<<dim3(S_ / 256, T_ / 128, B_), 512, SMB>>>(
        qp2, enc2, weights, nullptr, nullptr,
        I_, 2 * I_, 2 * I_, I_, I_,
        (long long)T_ * 2 * I_, (long long)S_ * 2 * I_, (long long)T_ * S_,
        S_, 0);

    // --- Softmax + fused fp16 split -> w2 ---
    softmax_mask<<<M_, 256>>>(weights, mask, w2);

    // --- GEMM4: ctx[b] = w[b] . encT[b]^T -> cat2 (ctx cols [0,1024)) ---
    tgemm<2><<<dim3(I_ / 256, T_ / 128, B_), 512, SMB>>>(
        w2, encT2, nullptr, cat2, nullptr,
        S_, 2 * S_, 2 * S_, S_, S_,
        (long long)T_ * 2 * S_, (long long)I_ * 2 * S_, (long long)T_ * 2 * C_,
        2 * C_, C_);

    // --- GEMM5: out = tanh(cat . W_out^T + b) ---
    tgemm<1><<<dim3(O_ / 256, M_ / 128, 1), 512, SMB>>>(
        cat2, wo2, out, nullptr, b_out,
        C_, 2 * C_, 2 * C_, C_, C_,
        0, 0, 0, O_, 0);
}

// round 9
// speedup vs baseline: 1.3597x; 1.3597x over previous
#include <cuda_runtime.h>
#include <cuda_fp16.h>
#include <math.h>
#include <stdint.h>

// ============================================================================
// Problem dims
// ============================================================================
#define B_ 64
#define T_ 128
#define S_ 1024
#define I_ 1024
#define O_ 1024
#define M_ (B_*T_)   // 8192
#define C_ (I_+O_)   // 2048

// ============================================================================
// Scratch (__device__ globals). fp16 2-way splits (h|l slabs).
// ============================================================================
__device__ __half g_wa2[I_ * 2 * O_];                    // [1024, 2048]
__device__ __half g_qp2[M_ * 2 * I_];                    // [8192, 2048]
__device__ __half g_enc2[(size_t)B_ * S_ * 2 * I_];      // [64][1024, 2048]
__device__ __half g_encT2[(size_t)B_ * I_ * 2 * S_];     // [64][1024, 2048] transposed
__device__ __half g_w2[M_ * 2 * S_];                     // [8192, 2048]
__device__ __half g_cat2[(size_t)M_ * 2 * C_];           // [8192, 4096] row=[ctx_h|dec_h|ctx_l|dec_l]
__device__ __half g_wo2[O_ * 2 * C_];                    // [1024, 4096]

// ============================================================================
// Helpers
// ============================================================================
__device__ __forceinline__ uint32_t smem_u32(const void* p) {
    uint32_t a;
    asm("{ .reg .u64 t; cvta.to.shared.u64 t, %1; cvt.u32.u64 %0, t; }" : "=r"(a) : "l"(p));
    return a;
}

__device__ __forceinline__ void ldsm4(uint32_t r[4], uint32_t addr) {
    asm volatile("ldmatrix.sync.aligned.m8n8.x4.shared.b16 {%0,%1,%2,%3}, [%4];"
        : "=r"(r[0]), "=r"(r[1]), "=r"(r[2]), "=r"(r[3]) : "r"(addr));
}

__device__ __forceinline__ void mma_fp16(float d[4], const uint32_t a[4], const uint32_t b[2]) {
    asm volatile(
        "mma.sync.aligned.m16n8k16.row.col.f32.f16.f16.f32 "
        "{%0,%1,%2,%3}, {%4,%5,%6,%7}, {%8,%9}, {%0,%1,%2,%3};"
        : "+f"(d[0]), "+f"(d[1]), "+f"(d[2]), "+f"(d[3])
        : "r"(a[0]), "r"(a[1]), "r"(a[2]), "r"(a[3]), "r"(b[0]), "r"(b[1]));
}

__device__ __forceinline__ void split2h(float x, __half& h, __half& l) {
    h = __float2half_rn(x);
    l = __float2half_rn(x - __half2float(h));
}

#define CP_ASYNC16(dst, src) \
    asm volatile("cp.async.cg.shared.global [%0], [%1], 16;" :: "r"(dst), "l"(src))
#define CP_COMMIT() asm volatile("cp.async.commit_group;" ::: "memory")
#define CP_WAIT1()  asm volatile("cp.async.wait_group 1;" ::: "memory")
#define CP_WAIT0()  asm volatile("cp.async.wait_group 0;" ::: "memory")

// ============================================================================
// HMMA GEMM, fp16 2-way split (3 passes: hh, hl, lh), NT, K-major.
// A[rows, pitchA] slabs at s*slabA; B[rows, pitchB] slabs at s*slabB.
// CTA tile 128x128, BK=64, 2-stage cp.async, 256 threads (8 warps 2x4),
// warp tile 64x32.
// EPI: 0 = fp32 store, 1 = tanh(acc+bias) fp32, 2 = split2h half store
// ============================================================================
#define TILEB 16384                     // 128x64 half tile bytes
#define STAGEB (4*TILEB)                // 2 A-slabs + 2 B-slabs = 65536

template<int EPI>
__global__ void __launch_bounds__(256) tgemm(
    const __half* __restrict__ A, const __half* __restrict__ B,
    float* __restrict__ Cf, __half* __restrict__ Cs,
    const float* __restrict__ bias,
    int K, int pitchA, int pitchB, int slabA, int slabB,
    long long sA, long long sB, long long sC,
    int ldc, int splitOff)
{
    extern __shared__ char smem[];
    const uint32_t sb = smem_u32(smem);
    const int tid = threadIdx.x;
    const int lane = tid & 31, wid = tid >> 5;
    const int wm = wid & 1, wn = wid >> 1;         // warp tile (wm*64, wn*32)
    const int n0 = blockIdx.x * 128, m0 = blockIdx.y * 128;
    const long long z = blockIdx.z;

    const __half* Ab = A + z * sA;
    const __half* Bb = B + z * sB;

    const int PA[3] = {0, 0, 1};
    const int PB[3] = {0, 1, 0};

    const int nchunk = K >> 6;

    float acc[4][4][4];
    #pragma unroll
    for (int i = 0; i < 4; i++)
        #pragma unroll
        for (int j = 0; j < 4; j++)
            #pragma unroll
            for (int q = 0; q < 4; q++) acc[i][j][q] = 0.f;

    // ldmatrix lane-address components
    const int g = lane >> 3, lr = lane & 7;
    const int a_r  = lr + (g & 1) * 8;
    const int a_kb = (g >> 1) * 16;
    const int b_r  = lr + (g >> 1) * 8;
    const int b_kb = (g & 1) * 16;

    auto prefetch = [&](int c, int stage) {
        const int k0 = c << 6;
        const uint32_t sbase = sb + stage * STAGEB;
        #pragma unroll
        for (int s = 0; s < 2; s++) {
            #pragma unroll
            for (int j = 0; j < 4; j++) {       // A slab: 128x64
                int v = tid + 256 * j;
                int r = v >> 3, cc = (v & 7) << 3;
                uint32_t off = (uint32_t)(r * 128 + cc * 2);
                off ^= (off >> 3) & 0x70u;
                CP_ASYNC16(sbase + s * TILEB + off,
                           Ab + (long long)(m0 + r) * pitchA + s * slabA + k0 + cc);
            }
            #pragma unroll
            for (int j = 0; j < 4; j++) {       // B slab: 128x64
                int v = tid + 256 * j;
                int r = v >> 3, cc = (v & 7) << 3;
                uint32_t off = (uint32_t)(r * 128 + cc * 2);
                off ^= (off >> 3) & 0x70u;
                CP_ASYNC16(sbase + (2 + s) * TILEB + off,
                           Bb + (long long)(n0 + r) * pitchB + s * slabB + k0 + cc);
            }
        }
    };

    prefetch(0, 0);
    CP_COMMIT();

    for (int c = 0; c < nchunk; c++) {
        const int stage = c & 1;
        if (c + 1 < nchunk) {
            prefetch(c + 1, stage ^ 1);
            CP_COMMIT();
            CP_WAIT1();
        } else {
            CP_WAIT0();
        }
        __syncthreads();

        const uint32_t sbase = sb + stage * STAGEB;
        #pragma unroll
        for (int p = 0; p < 3; p++) {
            const uint32_t aBase = sbase + PA[p] * TILEB;
            const uint32_t bBase = sbase + (2 + PB[p]) * TILEB;
            #pragma unroll
            for (int kt = 0; kt < 4; kt++) {
                uint32_t afr[4][4], bfr[2][4];
                #pragma unroll
                for (int mt = 0; mt < 4; mt++) {
                    uint32_t off = (uint32_t)((wm * 64 + mt * 16 + a_r) * 128 + kt * 32 + a_kb);
                    off ^= (off >> 3) & 0x70u;
                    ldsm4(afr[mt], aBase + off);
                }
                #pragma unroll
                for (int ntp = 0; ntp < 2; ntp++) {
                    uint32_t off = (uint32_t)((wn * 32 + ntp * 16 + b_r) * 128 + kt * 32 + b_kb);
                    off ^= (off >> 3) & 0x70u;
                    ldsm4(bfr[ntp], bBase + off);
                }
                #pragma unroll
                for (int mt = 0; mt < 4; mt++)
                    #pragma unroll
                    for (int nt = 0; nt < 4; nt++)
                        mma_fp16(acc[mt][nt], afr[mt], &bfr[nt >> 1][(nt & 1) * 2]);
            }
        }
        __syncthreads();
    }

    // ---- epilogue ----
    const int qr = lane >> 2;
    const int qc = (lane & 3) * 2;
    #pragma unroll
    for (int mt = 0; mt < 4; mt++) {
        #pragma unroll
        for (int nt = 0; nt < 4; nt++) {
            const long long row0 = m0 + wm * 64 + mt * 16 + qr;
            const long long row1 = row0 + 8;
            const int col = n0 + wn * 32 + nt * 8 + qc;
            float v00 = acc[mt][nt][0], v01 = acc[mt][nt][1];
            float v10 = acc[mt][nt][2], v11 = acc[mt][nt][3];
            if (EPI == 0) {
                *reinterpret_cast<float2*>(Cf + z * sC + row0 * ldc + col) = make_float2(v00, v01);
                *reinterpret_cast<float2*>(Cf + z * sC + row1 * ldc + col) = make_float2(v10, v11);
            } else if (EPI == 1) {
                float b0 = bias[col], b1 = bias[col + 1];
                *reinterpret_cast<float2*>(Cf + z * sC + row0 * ldc + col) =
                    make_float2(tanhf(v00 + b0), tanhf(v01 + b1));
                *reinterpret_cast<float2*>(Cf + z * sC + row1 * ldc + col) =
                    make_float2(tanhf(v10 + b0), tanhf(v11 + b1));
            } else {
                __half h0, l0, h1, l1;
                split2h(v00, h0, l0); split2h(v01, h1, l1);
                *reinterpret_cast<__half2*>(Cs + z * sC + row0 * ldc + col) = __halves2half2(h0, h1);
                *reinterpret_cast<__half2*>(Cs + z * sC + row0 * ldc + splitOff + col) = __halves2half2(l0, l1);
                split2h(v10, h0, l0); split2h(v11, h1, l1);
                *reinterpret_cast<__half2*>(Cs + z * sC + row1 * ldc + col) = __halves2half2(h0, h1);
                *reinterpret_cast<__half2*>(Cs + z * sC + row1 * ldc + splitOff + col) = __halves2half2(l0, l1);
            }
        }
    }
}

// ============================================================================
// Conversion kernels (fp16 2-way)
// ============================================================================
__global__ void __launch_bounds__(256) split2_kernel(
    const float* __restrict__ src, __half* __restrict__ dst, int K)
{
    long long i = (long long)blockIdx.x * blockDim.x + threadIdx.x;
    long long rr = i / K;
    int k = (int)(i - rr * K);
    __half h, l;
    split2h(src[i], h, l);
    __half* row = dst + rr * (2LL * K);
    row[k] = h; row[K + k] = l;
}

// dec -> cat2 [8192,4096]: row = [ctx_h(0:1024)|dec_h(1024:2048)|ctx_l(2048:3072)|dec_l(3072:4096)]
__global__ void __launch_bounds__(256) dec_to_cat_kernel(
    const float* __restrict__ dec, __half* __restrict__ cat)
{
    long long i = (long long)blockIdx.x * blockDim.x + threadIdx.x;  // 8192*1024
    long long m = i >> 10;
    int o = (int)(i & 1023);
    __half h, l;
    split2h(dec[i], h, l);
    cat[m * 4096 + 1024 + o] = h;
    cat[m * 4096 + 3072 + o] = l;
}

// enc -> enc2 [b][s, 2048] and encT2 [b][i, 2048] (transposed), h|l
__global__ void __launch_bounds__(1024) enc_split_kernel(
    const float* __restrict__ enc, __half* __restrict__ e2, __half* __restrict__ eT2)
{
    __shared__ __half sh[32][33], sl[32][33];
    int b = blockIdx.z;
    int i0 = blockIdx.x * 32, s0 = blockIdx.y * 32;
    int tx = threadIdx.x, ty = threadIdx.y;
    const float* eb = enc + (size_t)b * S_ * I_;
    float x = eb[(size_t)(s0 + ty) * I_ + i0 + tx];
    __half h, l;
    split2h(x, h, l);
    __half* e2b = e2 + (size_t)b * S_ * 2 * I_;
    e2b[(size_t)(s0 + ty) * 2048 + i0 + tx] = h;
    e2b[(size_t)(s0 + ty) * 2048 + 1024 + i0 + tx] = l;
    sh[ty][tx] = h; sl[ty][tx] = l;
    __syncthreads();
    __half* eTb = eT2 + (size_t)b * I_ * 2 * S_;
    eTb[(size_t)(i0 + ty) * 2048 + s0 + tx] = sh[tx][ty];
    eTb[(size_t)(i0 + ty) * 2048 + 1024 + s0 + tx] = sl[tx][ty];
}

// ============================================================================
// Masked softmax over rows of [B*T, S=1024], in place (fp32), fused fp16 split.
// ============================================================================
__device__ __forceinline__ float warpMax(float v) {
    #pragma unroll
    for (int o = 16; o; o >>= 1) v = fmaxf(v, __shfl_xor_sync(0xffffffffu, v, o));
    return v;
}
__device__ __forceinline__ float warpSum(float v) {
    #pragma unroll
    for (int o = 16; o; o >>= 1) v += __shfl_xor_sync(0xffffffffu, v, o);
    return v;
}

__global__ void __launch_bounds__(256) softmax_mask(
    float* __restrict__ w, const int* __restrict__ mask, __half* __restrict__ wsplit)
{
    const int S = 1024;
    long long row = blockIdx.x;
    int b = (int)(row >> 7);
    float* sr = w + row * S;
    const int* mr = mask + (long long)b * S;
    int tid = threadIdx.x;

    float4 v = *reinterpret_cast<const float4*>(sr + tid * 4);
    int4 m = *reinterpret_cast<const int4*>(mr + tid * 4);

    bool msk[4] = {m.x != 0, m.y != 0, m.z != 0, m.w != 0};
    float x[4];
    x[0] = msk[0] ? -INFINITY : v.x;
    x[1] = msk[1] ? -INFINITY : v.y;
    x[2] = msk[2] ? -INFINITY : v.z;
    x[3] = msk[3] ? -INFINITY : v.w;

    float mx = fmaxf(fmaxf(x[0], x[1]), fmaxf(x[2], x[3]));

    __shared__ float sh[8];
    float wm = warpMax(mx);
    if ((tid & 31) == 0) sh[tid >> 5] = wm;
    __syncthreads();
    if (tid < 32) {
        float t = (tid < 8) ? sh[tid] : -INFINITY;
        t = warpMax(t);
        if (tid == 0) sh[0] = t;
    }
    __syncthreads();
    mx = sh[0];

    float e[4], s = 0.f;
    #pragma unroll
    for (int j = 0; j < 4; j++) {
        e[j] = msk[j] ? 0.f : __expf(x[j] - mx);
        s += e[j];
    }
    __syncthreads();
    float ws = warpSum(s);
    if ((tid & 31) == 0) sh[tid >> 5] = ws;
    __syncthreads();
    if (tid < 32) {
        float t = (tid < 8) ? sh[tid] : 0.f;
        t = warpSum(t);
        if (tid == 0) sh[0] = t;
    }
    __syncthreads();
    float inv = 1.0f / sh[0];

    float o[4] = {e[0] * inv, e[1] * inv, e[2] * inv, e[3] * inv};
    float4 of = {o[0], o[1], o[2], o[3]};
    *reinterpret_cast<float4*>(sr + tid * 4) = of;

    __half* wrow = wsplit + row * 2048;
    #pragma unroll
    for (int j = 0; j < 4; j++) {
        __half h, l;
        split2h(o[j], h, l);
        wrow[tid * 4 + j] = h;
        wrow[1024 + tid * 4 + j] = l;
    }
}

// ============================================================================
extern "C" void kernel_launch(void* const* d_in, const int* in_sizes, int n_in,
                              void* d_out, int out_size)
{
    const float* dec    = (const float*)d_in[0];   // [64,128,1024]
    const float* enc    = (const float*)d_in[1];   // [64,1024,1024]
    const int*   mask   = (const int*)d_in[2];     // [64,1024] bool->int32
    const float* W_attn = (const float*)d_in[3];   // [1024,1024]
    const float* W_out  = (const float*)d_in[4];   // [1024,2048]
    const float* b_out  = (const float*)d_in[5];   // [1024]

    float* out     = (float*)d_out;                 // attn_outputs [64,128,1024]
    float* weights = out + (long long)M_ * O_;      // attn_weights [64,128,1024]

    __half *wa2, *qp2, *enc2, *encT2, *w2, *cat2, *wo2;
    cudaGetSymbolAddress((void**)&wa2,   g_wa2);
    cudaGetSymbolAddress((void**)&qp2,   g_qp2);
    cudaGetSymbolAddress((void**)&enc2,  g_enc2);
    cudaGetSymbolAddress((void**)&encT2, g_encT2);
    cudaGetSymbolAddress((void**)&w2,    g_w2);
    cudaGetSymbolAddress((void**)&cat2,  g_cat2);
    cudaGetSymbolAddress((void**)&wo2,   g_wo2);

    const int SMB = 2 * STAGEB;  // 131072 (2 stages x 4 tiles)
    cudaFuncSetAttribute((const void*)tgemm<0>, cudaFuncAttributeMaxDynamicSharedMemorySize, SMB);
    cudaFuncSetAttribute((const void*)tgemm<1>, cudaFuncAttributeMaxDynamicSharedMemorySize, SMB);
    cudaFuncSetAttribute((const void*)tgemm<2>, cudaFuncAttributeMaxDynamicSharedMemorySize, SMB);

    // --- Conversions ---
    split2_kernel<<<(I_ * (long long)O_) / 256, 256>>>(W_attn, wa2, O_);
    split2_kernel<<<(O_ * (long long)C_) / 256, 256>>>(W_out, wo2, C_);
    enc_split_kernel<<<dim3(I_ / 32, S_ / 32, B_), dim3(32, 32)>>>(enc, enc2, encT2);
    dec_to_cat_kernel<<<(M_ * (long long)O_) / 256, 256>>>(dec, cat2);

    // --- GEMM1: q_proj = dec . W_attn^T  (A = dec slabs inside cat2) -> qp2 ---
    tgemm<2><<<dim3(I_ / 128, M_ / 128, 1), 256, SMB>>>(
        cat2 + 1024, wa2, nullptr, qp2, nullptr,
        O_, /*pitchA*/4096, /*pitchB*/2048, /*slabA*/2048, /*slabB*/1024,
        0, 0, 0, 2 * I_, I_);

    // --- GEMM2: scores[b] = q[b] . enc[b]^T -> weights fp32 ---
    tgemm<0><<<dim3(S_ / 128, T_ / 128, B_), 256, SMB>>>(
        qp2, enc2, weights, nullptr, nullptr,
        I_, 2 * I_, 2 * I_, I_, I_,
        (long long)T_ * 2 * I_, (long long)S_ * 2 * I_, (long long)T_ * S_,
        S_, 0);

    // --- Softmax + fused fp16 split -> w2 ---
    softmax_mask<<<M_, 256>>>(weights, mask, w2);

    // --- GEMM4: ctx[b] = w[b] . encT[b]^T -> cat2 (ctx cols [0,1024)) ---
    tgemm<2><<<dim3(I_ / 128, T_ / 128, B_), 256, SMB>>>(
        w2, encT2, nullptr, cat2, nullptr,
        S_, 2 * S_, 2 * S_, S_, S_,
        (long long)T_ * 2 * S_, (long long)I_ * 2 * S_, (long long)T_ * 2 * C_,
        2 * C_, C_);

    // --- GEMM5: out = tanh(cat . W_out^T + b) ---
    tgemm<1><<<dim3(O_ / 128, M_ / 128, 1), 256, SMB>>>(
        cat2, wo2, out, nullptr, b_out,
        C_, 2 * C_, 2 * C_, C_, C_,
        0, 0, 0, O_, 0);
}